// round 1
// baseline (speedup 1.0000x reference)
#include <cuda_runtime.h>
#include <math.h>

// Problem constants
#define B_Q    1024
#define NCORP  262144
#define KDIM   256
#define DMODEL 1024
#define TOPK   8

// Score kernel tiling
#define TM      128                 // queries per CTA
#define TN      128                 // corpus cols per n-tile
#define KSLAB   32
#define NSLABS  (KDIM / KSLAB)      // 8
#define NCHUNKS 128
#define CHUNK   (NCORP / NCHUNKS)   // 2048 cols per CTA
#define NTILES  (CHUNK / TN)        // 16
#define QTILES  (B_Q / TM)          // 8

#define SA_FLOATS (KDIM * TM)            // 32768  (A resident, [k][m])
#define SB_FLOATS (2 * KSLAB * TN)       // 8192   (B double buffer, [k][n])
#define SS_PITCH  132
#define SS_FLOATS (64 * SS_PITCH)        // 8448   (half score tile staging)
#define SMEM_BYTES ((SA_FLOATS + SB_FLOATS + SS_FLOATS) * 4)  // 197632

// ---- device-global scratch (no allocations allowed) ----
__device__ float g_qnT[KDIM * B_Q];              // normalized queries, transposed [k][q]
__device__ float g_crinv[NCORP];                 // 1/max(||key||,eps)
__device__ float g_keysT[67108864];              // normalized keys, transposed [k][n]  (256MB)
__device__ float g_pscore[B_Q * NCHUNKS * TOPK]; // per-chunk top-8 partial scores
__device__ int   g_pidx[B_Q * NCHUNKS * TOPK];
__device__ int   g_topidx[B_Q * TOPK];

__device__ __forceinline__ bool better(float s1, int i1, float s2, int i2) {
    return (s1 > s2) || (s1 == s2 && i1 < i2);
}

__device__ __forceinline__ void topk_insert(float ts[TOPK], int ti[TOPK], float v, int c) {
    ts[7] = v; ti[7] = c;
#pragma unroll
    for (int j = 7; j > 0; j--) {
        if (better(ts[j], ti[j], ts[j - 1], ti[j - 1])) {
            float tf = ts[j]; ts[j] = ts[j - 1]; ts[j - 1] = tf;
            int   tt = ti[j]; ti[j] = ti[j - 1]; ti[j - 1] = tt;
        }
    }
}

// ---- kernel 1: normalize queries, write transposed [k][q] ----
__global__ void qnorm_kernel(const float* __restrict__ q) {
    int row  = (blockIdx.x * blockDim.x + threadIdx.x) >> 5;   // 1024 warps total
    int lane = threadIdx.x & 31;
    if (row >= B_Q) return;
    float x[8];
    *(float4*)&x[0] = *(const float4*)(q + row * KDIM + lane * 8);
    *(float4*)&x[4] = *(const float4*)(q + row * KDIM + lane * 8 + 4);
    float ss = 0.f;
#pragma unroll
    for (int e = 0; e < 8; e++) ss += x[e] * x[e];
#pragma unroll
    for (int o = 16; o > 0; o >>= 1) ss += __shfl_xor_sync(0xffffffffu, ss, o);
    float d = fmaxf(sqrtf(ss), 1e-12f);
#pragma unroll
    for (int e = 0; e < 8; e++)
        g_qnT[(lane * 8 + e) * B_Q + row] = x[e] / d;
}

// ---- kernel 2: corpus reciprocal norms ----
__global__ void crnorm_kernel(const float* __restrict__ keys) {
    int row  = (blockIdx.x * blockDim.x + threadIdx.x) >> 5;
    int lane = threadIdx.x & 31;
    if (row >= NCORP) return;
    float4 a = *(const float4*)(keys + (size_t)row * KDIM + lane * 8);
    float4 b = *(const float4*)(keys + (size_t)row * KDIM + lane * 8 + 4);
    float ss = a.x*a.x + a.y*a.y + a.z*a.z + a.w*a.w
             + b.x*b.x + b.y*b.y + b.z*b.z + b.w*b.w;
#pragma unroll
    for (int o = 16; o > 0; o >>= 1) ss += __shfl_xor_sync(0xffffffffu, ss, o);
    if (lane == 0) g_crinv[row] = 1.0f / fmaxf(sqrtf(ss), 1e-12f);
}

// ---- kernel 3: normalize + transpose corpus keys -> [k][n] ----
__global__ void transpose_kernel(const float* __restrict__ keys) {
    __shared__ float tile[32][33];
    int r0 = blockIdx.x * 32;
    int k0 = blockIdx.y * 32;
    int tx = threadIdx.x, ty = threadIdx.y;   // block (32, 8)
#pragma unroll
    for (int j = 0; j < 4; j++) {
        int r = r0 + ty + j * 8;
        tile[ty + j * 8][tx] = keys[(size_t)r * KDIM + k0 + tx] * g_crinv[r];
    }
    __syncthreads();
#pragma unroll
    for (int j = 0; j < 4; j++) {
        int k = k0 + ty + j * 8;
        g_keysT[(size_t)k * NCORP + r0 + tx] = tile[tx][ty + j * 8];
    }
}

// ---- kernel 4: fused similarity GEMM + per-chunk top-8 ----
__global__ __launch_bounds__(256, 1) void score_topk_kernel() {
    extern __shared__ float smem[];
    float* sA = smem;                         // [KDIM][TM]
    float* sB = smem + SA_FLOATS;             // [2][KSLAB][TN]
    float* sS = smem + SA_FLOATS + SB_FLOATS; // [64][SS_PITCH]

    const int t  = threadIdx.x;
    const int tx = t & 15, ty = t >> 4;
    const int qtile = blockIdx.x, chunk = blockIdx.y;
    const int q0 = qtile * TM;
    const int c0 = chunk * CHUNK;

    // Resident A fill: coalesced from g_qnT, conflict-free STS.
    for (int u = t; u < SA_FLOATS / 4; u += 256) {
        int k = u >> 5, mg = u & 31;
        *(float4*)(sA + k * TM + mg * 4) =
            *(const float4*)(g_qnT + k * B_Q + q0 + mg * 4);
    }

    // per-thread top-8 state: thread t owns query q0 + (t>>1), half h = t&1
    float ts[TOPK]; int ti[TOPK];
#pragma unroll
    for (int j = 0; j < TOPK; j++) { ts[j] = -INFINITY; ti[j] = 0x7fffffff; }
    const int qown = t >> 1;
    const int h = t & 1;

    __syncthreads();

    for (int nt = 0; nt < NTILES; nt++) {
        const int cbase = c0 + nt * TN;
        float acc[8][8];
#pragma unroll
        for (int i = 0; i < 8; i++)
#pragma unroll
            for (int j = 0; j < 8; j++) acc[i][j] = 0.f;

        // prologue: slab 0
        float4 st[4];
#pragma unroll
        for (int it = 0; it < 4; it++) {
            int u = it * 256 + t; int k = u >> 5; int cg = u & 31;
            st[it] = *(const float4*)(g_keysT + (size_t)k * NCORP + cbase + cg * 4);
        }
#pragma unroll
        for (int it = 0; it < 4; it++) {
            int u = it * 256 + t; int k = u >> 5; int cg = u & 31;
            *(float4*)(sB + k * TN + cg * 4) = st[it];
        }
        __syncthreads();

        for (int ks = 0; ks < NSLABS; ks++) {
            const int cur = ks & 1;
            if (ks < NSLABS - 1) {
#pragma unroll
                for (int it = 0; it < 4; it++) {
                    int u = it * 256 + t; int k = u >> 5; int cg = u & 31;
                    st[it] = *(const float4*)(g_keysT +
                              (size_t)((ks + 1) * KSLAB + k) * NCORP + cbase + cg * 4);
                }
            }
            const float* sAc = sA + ks * KSLAB * TM;
            const float* sBc = sB + cur * (KSLAB * TN);
#pragma unroll 4
            for (int k = 0; k < KSLAB; k++) {
                float a[8], b[8];
                *(float4*)&a[0] = *(const float4*)(sAc + k * TM + ty * 8);
                *(float4*)&a[4] = *(const float4*)(sAc + k * TM + ty * 8 + 4);
                *(float4*)&b[0] = *(const float4*)(sBc + k * TN + tx * 8);
                *(float4*)&b[4] = *(const float4*)(sBc + k * TN + tx * 8 + 4);
#pragma unroll
                for (int i = 0; i < 8; i++)
#pragma unroll
                    for (int j = 0; j < 8; j++)
                        acc[i][j] = fmaf(a[i], b[j], acc[i][j]);
            }
            if (ks < NSLABS - 1) {
#pragma unroll
                for (int it = 0; it < 4; it++) {
                    int u = it * 256 + t; int k = u >> 5; int cg = u & 31;
                    *(float4*)(sB + (1 - cur) * (KSLAB * TN) + k * TN + cg * 4) = st[it];
                }
            }
            __syncthreads();
        }

        // epilogue half 0: rows 0..63
        if (ty < 8) {
#pragma unroll
            for (int i = 0; i < 8; i++) {
                int row = ty * 8 + i;
                *(float4*)(sS + row * SS_PITCH + tx * 8)     = *(float4*)&acc[i][0];
                *(float4*)(sS + row * SS_PITCH + tx * 8 + 4) = *(float4*)&acc[i][4];
            }
        }
        __syncthreads();
        if (t < 128) {
            const float* rowp = sS + qown * SS_PITCH + h * 64;
            const int cb2 = cbase + h * 64;
#pragma unroll 8
            for (int i = 0; i < 64; i++) {
                float v = rowp[i];
                if (better(v, cb2 + i, ts[7], ti[7])) topk_insert(ts, ti, v, cb2 + i);
            }
        }
        __syncthreads();
        // epilogue half 1: rows 64..127
        if (ty >= 8) {
#pragma unroll
            for (int i = 0; i < 8; i++) {
                int row = ty * 8 + i - 64;
                *(float4*)(sS + row * SS_PITCH + tx * 8)     = *(float4*)&acc[i][0];
                *(float4*)(sS + row * SS_PITCH + tx * 8 + 4) = *(float4*)&acc[i][4];
            }
        }
        __syncthreads();
        if (t >= 128) {
            const float* rowp = sS + (qown - 64) * SS_PITCH + h * 64;
            const int cb2 = cbase + h * 64;
#pragma unroll 8
            for (int i = 0; i < 64; i++) {
                float v = rowp[i];
                if (better(v, cb2 + i, ts[7], ti[7])) topk_insert(ts, ti, v, cb2 + i);
            }
        }
        __syncthreads();
    }

    // CTA-level merge of the two per-query thread lists -> per-chunk top-8
    float* ms = sS;                 // 2048 floats
    int*   mi = (int*)(sS + 2048);  // 2048 ints
#pragma unroll
    for (int j = 0; j < TOPK; j++) { ms[t * TOPK + j] = ts[j]; mi[t * TOPK + j] = ti[j]; }
    __syncthreads();
    if (h == 0) {
        int a = t * TOPK, b2 = (t + 1) * TOPK;
        int pa = 0, pb = 0;
        size_t base = ((size_t)(q0 + qown) * NCHUNKS + chunk) * TOPK;
#pragma unroll
        for (int j = 0; j < TOPK; j++) {
            float va = ms[a + pa], vb = ms[b2 + pb];
            int   ia = mi[a + pa], ib = mi[b2 + pb];
            bool takeA = better(va, ia, vb, ib);
            g_pscore[base + j] = takeA ? va : vb;
            g_pidx[base + j]   = takeA ? ia : ib;
            if (takeA) pa++; else pb++;
        }
    }
}

// ---- kernel 5: merge per-chunk partials -> global top-8, write scores ----
__global__ void final_merge_kernel(float* __restrict__ out_scores) {
    int q = blockIdx.x * blockDim.x + threadIdx.x;
    if (q >= B_Q) return;
    float ts[TOPK]; int ti[TOPK];
#pragma unroll
    for (int j = 0; j < TOPK; j++) { ts[j] = -INFINITY; ti[j] = 0x7fffffff; }
    const float* ps = g_pscore + (size_t)q * NCHUNKS * TOPK;
    const int*   pi = g_pidx   + (size_t)q * NCHUNKS * TOPK;
    for (int c = 0; c < NCHUNKS * TOPK; c++) {
        float v = ps[c]; int id = pi[c];
        if (better(v, id, ts[7], ti[7])) topk_insert(ts, ti, v, id);
    }
#pragma unroll
    for (int j = 0; j < TOPK; j++) {
        out_scores[q * TOPK + j] = ts[j];
        g_topidx[q * TOPK + j]   = ti[j];
    }
}

// ---- kernel 6: gather docs ----
__global__ void gather_kernel(const float* __restrict__ vals, float* __restrict__ out_docs) {
    int b = blockIdx.x;                 // 0..8191
    int idx = g_topidx[b];
    const float4* src = (const float4*)(vals + (size_t)idx * DMODEL);
    float4* dst = (float4*)(out_docs + (size_t)b * DMODEL);
    dst[threadIdx.x] = src[threadIdx.x];   // 256 threads * float4 = 1024 floats
}

extern "C" void kernel_launch(void* const* d_in, const int* in_sizes, int n_in,
                              void* d_out, int out_size) {
    const float* query = (const float*)d_in[0];
    const float* keys  = (const float*)d_in[1];
    const float* vals  = (const float*)d_in[2];
    float* out        = (float*)d_out;
    float* out_docs   = out;                                     // [1024,8,1024]
    float* out_scores = out + (size_t)B_Q * TOPK * DMODEL;       // [1024,8]

    qnorm_kernel<<<B_Q / 8, 256>>>(query);
    crnorm_kernel<<<NCORP / 8, 256>>>(keys);
    transpose_kernel<<<dim3(NCORP / 32, KDIM / 32), dim3(32, 8)>>>(keys);

    cudaFuncSetAttribute(score_topk_kernel,
                         cudaFuncAttributeMaxDynamicSharedMemorySize, SMEM_BYTES);
    score_topk_kernel<<<dim3(QTILES, NCHUNKS), 256, SMEM_BYTES>>>();

    final_merge_kernel<<<(B_Q + 255) / 256, 256>>>(out_scores);
    gather_kernel<<<B_Q * TOPK, 256>>>(vals, out_docs);
}

// round 2
// speedup vs baseline: 3.3609x; 3.3609x over previous
#include <cuda_runtime.h>
#include <cuda_bf16.h>
#include <math.h>

#define B_Q    1024
#define NCORP  262144
#define KDIM   256
#define DMODEL 1024
#define TOPK   8
#define LISTD  16          // per scan-thread candidate list depth
#define NCAND  32          // rescored candidates per query

#define TM      128
#define TN      128
#define KSLAB   64
#define NSLABS  4          // K=256 / 64
#define NCHUNKS 128
#define CHUNK   2048
#define NTILES  16         // CHUNK / TN
#define QTILES  8

#define LDA   264          // sA pitch (bf16): 33 x 16B units, conflict-free ldsm
#define LDB   72           // sB pitch (bf16): 9 x 16B units
#define LDSS  136          // sS pitch (bf16)

#define SA_ELE (TM * LDA)      // 33792 bf16
#define SB_ELE (TN * LDB)      // 9216 bf16 per buffer
#define SS_ELE (TM * LDSS)     // 17408 bf16
#define SMEM_BYTES ((SA_ELE + 2 * SB_ELE + SS_ELE) * 2)   // 139264

// ---- device-global scratch ----
__device__ __nv_bfloat16 g_qbf[B_Q * KDIM];
__device__ float         g_qn[B_Q * KDIM];
__device__ __nv_bfloat16 g_keysN[(size_t)NCORP * KDIM];     // 128 MB
__device__ float         g_pscore[B_Q * NCHUNKS * TOPK];
__device__ int           g_pidx[B_Q * NCHUNKS * TOPK];
__device__ int           g_cand[B_Q * NCAND];
__device__ int           g_topidx[B_Q * TOPK];

__device__ __forceinline__ bool better(float s1, int i1, float s2, int i2) {
    return (s1 > s2) || (s1 == s2 && i1 < i2);
}

__device__ __forceinline__ unsigned smem_u32(const void* p) {
    return (unsigned)__cvta_generic_to_shared(p);
}
__device__ __forceinline__ void ldsm_x4(unsigned* r, unsigned addr) {
    asm volatile("ldmatrix.sync.aligned.m8n8.x4.shared.b16 {%0,%1,%2,%3}, [%4];\n"
        : "=r"(r[0]), "=r"(r[1]), "=r"(r[2]), "=r"(r[3]) : "r"(addr));
}
__device__ __forceinline__ void mma16816(float* d, const unsigned* a, const unsigned* b) {
    asm volatile(
        "mma.sync.aligned.m16n8k16.row.col.f32.bf16.bf16.f32 "
        "{%0,%1,%2,%3}, {%4,%5,%6,%7}, {%8,%9}, {%0,%1,%2,%3};\n"
        : "+f"(d[0]), "+f"(d[1]), "+f"(d[2]), "+f"(d[3])
        : "r"(a[0]), "r"(a[1]), "r"(a[2]), "r"(a[3]), "r"(b[0]), "r"(b[1]));
}

// insert into sorted(desc) 16-deep register list (static indices only)
__device__ __forceinline__ void ins16(float ts[LISTD], int ti[LISTD], float v, int idx) {
    ts[15] = v; ti[15] = idx;
#pragma unroll
    for (int j = 15; j > 0; j--) {
        if (ts[j] > ts[j - 1]) {
            float tf = ts[j]; ts[j] = ts[j - 1]; ts[j - 1] = tf;
            int   tt = ti[j]; ti[j] = ti[j - 1]; ti[j - 1] = tt;
        }
    }
}

// ---- kernel 1: normalize queries -> fp32 + bf16, row-major ----
__global__ void qnorm_kernel(const float* __restrict__ q) {
    int row  = (blockIdx.x * blockDim.x + threadIdx.x) >> 5;
    int lane = threadIdx.x & 31;
    if (row >= B_Q) return;
    float x[8];
    *(float4*)&x[0] = *(const float4*)(q + row * KDIM + lane * 8);
    *(float4*)&x[4] = *(const float4*)(q + row * KDIM + lane * 8 + 4);
    float ss = 0.f;
#pragma unroll
    for (int e = 0; e < 8; e++) ss += x[e] * x[e];
#pragma unroll
    for (int o = 16; o > 0; o >>= 1) ss += __shfl_xor_sync(0xffffffffu, ss, o);
    float rinv = 1.0f / fmaxf(sqrtf(ss), 1e-12f);
    __nv_bfloat16 ob[8];
#pragma unroll
    for (int e = 0; e < 8; e++) {
        float v = x[e] * rinv;
        g_qn[row * KDIM + lane * 8 + e] = v;
        ob[e] = __float2bfloat16(v);
    }
    *(uint4*)(g_qbf + row * KDIM + lane * 8) = *(uint4*)ob;
}

// ---- kernel 2: normalize keys -> bf16 row-major (norm computed inline) ----
__global__ void keysprep_kernel(const float* __restrict__ keys) {
    int row  = (blockIdx.x * blockDim.x + threadIdx.x) >> 5;
    int lane = threadIdx.x & 31;
    if (row >= NCORP) return;
    float x[8];
    *(float4*)&x[0] = *(const float4*)(keys + (size_t)row * KDIM + lane * 8);
    *(float4*)&x[4] = *(const float4*)(keys + (size_t)row * KDIM + lane * 8 + 4);
    float ss = 0.f;
#pragma unroll
    for (int e = 0; e < 8; e++) ss += x[e] * x[e];
#pragma unroll
    for (int o = 16; o > 0; o >>= 1) ss += __shfl_xor_sync(0xffffffffu, ss, o);
    float rinv = 1.0f / fmaxf(sqrtf(ss), 1e-12f);
    __nv_bfloat16 ob[8];
#pragma unroll
    for (int e = 0; e < 8; e++) ob[e] = __float2bfloat16(x[e] * rinv);
    *(uint4*)(g_keysN + (size_t)row * KDIM + lane * 8) = *(uint4*)ob;
}

// ---- kernel 3: bf16 tensor-core GEMM + fused per-chunk approx top-8 ----
__global__ __launch_bounds__(256, 1) void score_kernel() {
    extern __shared__ char smem_raw[];
    __nv_bfloat16* sA = (__nv_bfloat16*)smem_raw;
    __nv_bfloat16* sB = sA + SA_ELE;             // 2 buffers
    __nv_bfloat16* sS = sB + 2 * SB_ELE;

    const int t = threadIdx.x, lane = t & 31, wid = t >> 5;
    const int wm = wid >> 2, wn = wid & 3;       // warp grid 2 (m) x 4 (n)
    const int q0 = blockIdx.x * TM, c0 = blockIdx.y * CHUNK;

    // resident A fill: 128 rows x 512B
#pragma unroll
    for (int i = 0; i < 16; i++) {
        int u = i * 256 + t; int row = u >> 5, seg = u & 31;
        *(uint4*)(sA + row * LDA + seg * 8) =
            *(const uint4*)(g_qbf + (q0 + row) * KDIM + seg * 8);
    }

    // per-thread candidate list (thread t owns query q0+(t>>1), half t&1)
    float ts[LISTD]; int ti[LISTD];
#pragma unroll
    for (int j = 0; j < LISTD; j++) { ts[j] = -INFINITY; ti[j] = 0x7fffffff; }
    float thr = -INFINITY;
    const int qown = t >> 1, h = t & 1;

    // ldmatrix base addresses
    unsigned aAddr[4];
    {
        int r = lane & 15, c8 = lane >> 4;
#pragma unroll
        for (int mi = 0; mi < 4; mi++)
            aAddr[mi] = smem_u32(sA + (wm * 64 + mi * 16 + r) * LDA + c8 * 8);
    }
    unsigned bBase[2][2];
    {
        int bn = (lane & 7) + ((lane >> 4) << 3);
        int bk = ((lane >> 3) & 1) * 8;
#pragma unroll
        for (int buf = 0; buf < 2; buf++)
#pragma unroll
            for (int np = 0; np < 2; np++)
                bBase[buf][np] = smem_u32(sB + buf * SB_ELE +
                                          (wn * 32 + np * 16 + bn) * LDB + bk);
    }

    __syncthreads();

    for (int nt = 0; nt < NTILES; nt++) {
        const int cbase = c0 + nt * TN;
        float acc[4][4][4];
#pragma unroll
        for (int mi = 0; mi < 4; mi++)
#pragma unroll
            for (int nf = 0; nf < 4; nf++)
#pragma unroll
                for (int e = 0; e < 4; e++) acc[mi][nf][e] = 0.f;

        // prologue: slab 0 -> buf 0
        uint4 ld[4];
#pragma unroll
        for (int i = 0; i < 4; i++) {
            int u = i * 256 + t; int row = u >> 3, seg = u & 7;
            ld[i] = *(const uint4*)(g_keysN + (size_t)(cbase + row) * KDIM + seg * 8);
        }
#pragma unroll
        for (int i = 0; i < 4; i++) {
            int u = i * 256 + t; int row = u >> 3, seg = u & 7;
            *(uint4*)(sB + row * LDB + seg * 8) = ld[i];
        }
        __syncthreads();

        for (int ks = 0; ks < NSLABS; ks++) {
            const int buf = ks & 1;
            if (ks < NSLABS - 1) {
#pragma unroll
                for (int i = 0; i < 4; i++) {
                    int u = i * 256 + t; int row = u >> 3, seg = u & 7;
                    ld[i] = *(const uint4*)(g_keysN + (size_t)(cbase + row) * KDIM +
                                            (ks + 1) * KSLAB + seg * 8);
                }
            }
#pragma unroll
            for (int kk4 = 0; kk4 < 4; kk4++) {
                unsigned af[4][4], bf[8];
                int aofs = (ks * KSLAB + kk4 * 16) * 2;   // bytes
                int bofs = (kk4 * 16) * 2;
#pragma unroll
                for (int mi = 0; mi < 4; mi++) ldsm_x4(af[mi], aAddr[mi] + aofs);
                ldsm_x4(&bf[0], bBase[buf][0] + bofs);
                ldsm_x4(&bf[4], bBase[buf][1] + bofs);
#pragma unroll
                for (int mi = 0; mi < 4; mi++)
#pragma unroll
                    for (int nf = 0; nf < 4; nf++)
                        mma16816(acc[mi][nf], af[mi], &bf[nf * 2]);
            }
            if (ks < NSLABS - 1) {
#pragma unroll
                for (int i = 0; i < 4; i++) {
                    int u = i * 256 + t; int row = u >> 3, seg = u & 7;
                    *(uint4*)(sB + (1 - buf) * SB_ELE + row * LDB + seg * 8) = ld[i];
                }
            }
            __syncthreads();
        }

        // stage accumulators to sS as bf16
#pragma unroll
        for (int mi = 0; mi < 4; mi++) {
#pragma unroll
            for (int nf = 0; nf < 4; nf++) {
                int r0 = wm * 64 + mi * 16 + (lane >> 2);
                int cc = wn * 32 + nf * 8 + (lane & 3) * 2;
                *(__nv_bfloat162*)(sS + r0 * LDSS + cc) =
                    __floats2bfloat162_rn(acc[mi][nf][0], acc[mi][nf][1]);
                *(__nv_bfloat162*)(sS + (r0 + 8) * LDSS + cc) =
                    __floats2bfloat162_rn(acc[mi][nf][2], acc[mi][nf][3]);
            }
        }
        __syncthreads();

        // scan: group-max filter (8 elems/group) then detail insert
        {
            const uint4* p = (const uint4*)(sS + qown * LDSS + h * 64);
#pragma unroll
            for (int g = 0; g < 8; g++) {
                uint4 v = p[g];
                __nv_bfloat162 x0 = *(__nv_bfloat162*)&v.x;
                __nv_bfloat162 x1 = *(__nv_bfloat162*)&v.y;
                __nv_bfloat162 x2 = *(__nv_bfloat162*)&v.z;
                __nv_bfloat162 x3 = *(__nv_bfloat162*)&v.w;
                __nv_bfloat162 m = __hmax2(__hmax2(x0, x1), __hmax2(x2, x3));
                float gm = fmaxf(__bfloat162float(m.x), __bfloat162float(m.y));
                if (gm > thr) {
                    int base = cbase + h * 64 + g * 8;
                    float e0 = __bfloat162float(x0.x), e1 = __bfloat162float(x0.y);
                    float e2 = __bfloat162float(x1.x), e3 = __bfloat162float(x1.y);
                    float e4 = __bfloat162float(x2.x), e5 = __bfloat162float(x2.y);
                    float e6 = __bfloat162float(x3.x), e7 = __bfloat162float(x3.y);
                    if (e0 > thr) ins16(ts, ti, e0, base + 0);
                    if (e1 > ts[15]) ins16(ts, ti, e1, base + 1);
                    if (e2 > ts[15]) ins16(ts, ti, e2, base + 2);
                    if (e3 > ts[15]) ins16(ts, ti, e3, base + 3);
                    if (e4 > ts[15]) ins16(ts, ti, e4, base + 4);
                    if (e5 > ts[15]) ins16(ts, ti, e5, base + 5);
                    if (e6 > ts[15]) ins16(ts, ti, e6, base + 6);
                    if (e7 > ts[15]) ins16(ts, ti, e7, base + 7);
                    thr = ts[15];
                }
            }
        }
        __syncthreads();
    }

    // CTA merge: per query combine the two 16-lists -> chunk top-8
    float* ms = (float*)sS;            // 256*16 floats = 16KB
    int*   mi2 = (int*)(ms + 256 * LISTD);
#pragma unroll
    for (int j = 0; j < LISTD; j++) { ms[t * LISTD + j] = ts[j]; mi2[t * LISTD + j] = ti[j]; }
    __syncthreads();
    if (h == 0) {
        int a = t * LISTD, b2 = (t + 1) * LISTD;
        int pa = 0, pb = 0;
        size_t base = ((size_t)(q0 + qown) * NCHUNKS + blockIdx.y) * TOPK;
#pragma unroll
        for (int j = 0; j < TOPK; j++) {
            float va = ms[a + pa], vb = ms[b2 + pb];
            int   ia = mi2[a + pa], ib = mi2[b2 + pb];
            bool takeA = better(va, ia, vb, ib);
            g_pscore[base + j] = takeA ? va : vb;
            g_pidx[base + j]   = takeA ? ia : ib;
            if (takeA) pa++; else pb++;
        }
    }
}

// ---- kernel 4: prune per-query 1024 chunk-candidates -> top-32 approx ----
__global__ void prune_kernel() {
    int q = blockIdx.x * blockDim.x + threadIdx.x;
    if (q >= B_Q) return;
    float ts[NCAND]; int ti[NCAND];
#pragma unroll
    for (int j = 0; j < NCAND; j++) { ts[j] = -INFINITY; ti[j] = 0x7fffffff; }
    const float* ps = g_pscore + (size_t)q * NCHUNKS * TOPK;
    const int*   pi = g_pidx   + (size_t)q * NCHUNKS * TOPK;
    for (int c = 0; c < NCHUNKS * TOPK; c++) {
        float v = ps[c];
        if (v > ts[NCAND - 1]) {
            ts[NCAND - 1] = v; ti[NCAND - 1] = pi[c];
#pragma unroll
            for (int j = NCAND - 1; j > 0; j--) {
                if (ts[j] > ts[j - 1]) {
                    float tf = ts[j]; ts[j] = ts[j - 1]; ts[j - 1] = tf;
                    int   tt = ti[j]; ti[j] = ti[j - 1]; ti[j - 1] = tt;
                }
            }
        }
    }
#pragma unroll
    for (int j = 0; j < NCAND; j++) g_cand[q * NCAND + j] = ti[j];
}

// ---- kernel 5: exact fp32 rescore of 32 candidates + final top-8 ----
__global__ __launch_bounds__(256) void rescore_kernel(const float* __restrict__ keys,
                                                      float* __restrict__ out_scores) {
    __shared__ float cs[NCAND];
    __shared__ int   ci[NCAND];
    int q = blockIdx.x;
    int wid = threadIdx.x >> 5, lane = threadIdx.x & 31;

    float qv[8];
    *(float4*)&qv[0] = *(const float4*)(g_qn + q * KDIM + lane * 8);
    *(float4*)&qv[4] = *(const float4*)(g_qn + q * KDIM + lane * 8 + 4);

    for (int c = wid; c < NCAND; c += 8) {
        int idx = g_cand[q * NCAND + c];
        float kv[8];
        *(float4*)&kv[0] = *(const float4*)(keys + (size_t)idx * KDIM + lane * 8);
        *(float4*)&kv[4] = *(const float4*)(keys + (size_t)idx * KDIM + lane * 8 + 4);
        float ss = 0.f, dt = 0.f;
#pragma unroll
        for (int e = 0; e < 8; e++) { ss += kv[e] * kv[e]; dt += kv[e] * qv[e]; }
#pragma unroll
        for (int o = 16; o > 0; o >>= 1) {
            ss += __shfl_xor_sync(0xffffffffu, ss, o);
            dt += __shfl_xor_sync(0xffffffffu, dt, o);
        }
        if (lane == 0) {
            cs[c] = dt / fmaxf(sqrtf(ss), 1e-12f);
            ci[c] = idx;
        }
    }
    __syncthreads();
    if (threadIdx.x == 0) {
        float ts[TOPK]; int ti[TOPK];
#pragma unroll
        for (int j = 0; j < TOPK; j++) { ts[j] = -INFINITY; ti[j] = 0x7fffffff; }
        for (int c = 0; c < NCAND; c++) {
            float v = cs[c]; int id = ci[c];
            if (better(v, id, ts[TOPK - 1], ti[TOPK - 1])) {
                ts[TOPK - 1] = v; ti[TOPK - 1] = id;
#pragma unroll
                for (int j = TOPK - 1; j > 0; j--) {
                    if (better(ts[j], ti[j], ts[j - 1], ti[j - 1])) {
                        float tf = ts[j]; ts[j] = ts[j - 1]; ts[j - 1] = tf;
                        int   tt = ti[j]; ti[j] = ti[j - 1]; ti[j - 1] = tt;
                    }
                }
            }
        }
#pragma unroll
        for (int j = 0; j < TOPK; j++) {
            out_scores[q * TOPK + j] = ts[j];
            g_topidx[q * TOPK + j]   = ti[j];
        }
    }
}

// ---- kernel 6: gather docs ----
__global__ void gather_kernel(const float* __restrict__ vals, float* __restrict__ out_docs) {
    int b = blockIdx.x;
    int idx = g_topidx[b];
    const float4* src = (const float4*)(vals + (size_t)idx * DMODEL);
    float4* dst = (float4*)(out_docs + (size_t)b * DMODEL);
    dst[threadIdx.x] = src[threadIdx.x];
}

extern "C" void kernel_launch(void* const* d_in, const int* in_sizes, int n_in,
                              void* d_out, int out_size) {
    const float* query = (const float*)d_in[0];
    const float* keys  = (const float*)d_in[1];
    const float* vals  = (const float*)d_in[2];
    float* out        = (float*)d_out;
    float* out_docs   = out;
    float* out_scores = out + (size_t)B_Q * TOPK * DMODEL;

    qnorm_kernel<<<B_Q / 8, 256>>>(query);
    keysprep_kernel<<<NCORP / 8, 256>>>(keys);

    cudaFuncSetAttribute(score_kernel,
                         cudaFuncAttributeMaxDynamicSharedMemorySize, SMEM_BYTES);
    score_kernel<<<dim3(QTILES, NCHUNKS), 256, SMEM_BYTES>>>();

    prune_kernel<<<4, 256>>>();
    rescore_kernel<<<B_Q, 256>>>(keys, out_scores);
    gather_kernel<<<B_Q * TOPK, 256>>>(vals, out_docs);
}

// round 4
// speedup vs baseline: 8.5921x; 2.5565x over previous
#include <cuda_runtime.h>
#include <cuda_bf16.h>
#include <math.h>
#include <stdint.h>

#define B_Q    1024
#define NCORP  262144
#define KDIM   256
#define DMODEL 1024
#define TOPK   8
#define NCAND  32

#define TM      128
#define TN      128
#define KSLAB   128
#define NCHUNKS 128
#define CHUNK   2048
#define NTILES  16
#define QTILES  8
#define NSLABS_TOTAL (NTILES * 2)    // 32 k-slabs streamed per CTA

// byte pitches (odd 16B-unit counts -> conflict-free ldsm)
#define LDA_B  528      // 33 units: 512B data + 16B pad
#define LDB_B  272      // 17 units: 256B data + 16B pad
#define LDS_B  272      // staging pitch (bf16 scores)

#define SM_A   0
#define A_BYTES (128 * LDA_B)              // 67584
#define SM_B   A_BYTES                      // 67584
#define SB_BYTES (128 * LDB_B)             // 34816 per buffer
#define SM_S   (SM_B + 2 * SB_BYTES)       // 137216
#define SS_BYTES (128 * LDS_B)             // 34816
#define SMEM_TOTAL (SM_S + SS_BYTES)       // 172032

// ---- device-global scratch ----
__device__ __nv_bfloat16 g_qbf[B_Q * KDIM];
__device__ float         g_qn[B_Q * KDIM];
__device__ __nv_bfloat16 g_keysN[(size_t)NCORP * KDIM];     // 128 MB
__device__ float         g_pscore[B_Q * NCHUNKS * TOPK];
__device__ int           g_pidx[B_Q * NCHUNKS * TOPK];
__device__ int           g_cand[B_Q * NCAND];
__device__ int           g_topidx[B_Q * TOPK];

__device__ __forceinline__ bool better(float s1, int i1, float s2, int i2) {
    return (s1 > s2) || (s1 == s2 && i1 < i2);
}
__device__ __forceinline__ uint32_t smem_u32(const void* p) {
    return (uint32_t)__cvta_generic_to_shared(p);
}
__device__ __forceinline__ void ldsm_x4(unsigned* r, unsigned addr) {
    asm volatile("ldmatrix.sync.aligned.m8n8.x4.shared.b16 {%0,%1,%2,%3}, [%4];\n"
        : "=r"(r[0]), "=r"(r[1]), "=r"(r[2]), "=r"(r[3]) : "r"(addr));
}
__device__ __forceinline__ void mma16816(float* d, const unsigned* a, const unsigned* b) {
    asm volatile(
        "mma.sync.aligned.m16n8k16.row.col.f32.bf16.bf16.f32 "
        "{%0,%1,%2,%3}, {%4,%5,%6,%7}, {%8,%9}, {%0,%1,%2,%3};\n"
        : "+f"(d[0]), "+f"(d[1]), "+f"(d[2]), "+f"(d[3])
        : "r"(a[0]), "r"(a[1]), "r"(a[2]), "r"(a[3]), "r"(b[0]), "r"(b[1]));
}
#define CP_ASYNC16(dst, src) \
    asm volatile("cp.async.cg.shared.global [%0], [%1], 16;" :: "r"(dst), "l"(src))
#define CP_COMMIT() asm volatile("cp.async.commit_group;" ::: "memory")
#define CP_WAIT1()  asm volatile("cp.async.wait_group 1;" ::: "memory")
#define CP_WAIT0()  asm volatile("cp.async.wait_group 0;" ::: "memory")

// value-sorted desc depth-8 insert (value only; final order fixed by rescore)
__device__ __forceinline__ void ins8(float ts[8], int ti[8], float v, int idx) {
    ts[7] = v; ti[7] = idx;
#pragma unroll
    for (int j = 7; j > 0; j--) {
        if (ts[j] > ts[j - 1]) {
            float tf = ts[j]; ts[j] = ts[j - 1]; ts[j - 1] = tf;
            int   tt = ti[j]; ti[j] = ti[j - 1]; ti[j - 1] = tt;
        }
    }
}

// ---- kernel 1: normalize queries -> fp32 + bf16 ----
__global__ void qnorm_kernel(const float* __restrict__ q) {
    int row  = (blockIdx.x * blockDim.x + threadIdx.x) >> 5;
    int lane = threadIdx.x & 31;
    if (row >= B_Q) return;
    float x[8];
    *(float4*)&x[0] = *(const float4*)(q + row * KDIM + lane * 8);
    *(float4*)&x[4] = *(const float4*)(q + row * KDIM + lane * 8 + 4);
    float ss = 0.f;
#pragma unroll
    for (int e = 0; e < 8; e++) ss += x[e] * x[e];
#pragma unroll
    for (int o = 16; o > 0; o >>= 1) ss += __shfl_xor_sync(0xffffffffu, ss, o);
    float rinv = 1.0f / fmaxf(sqrtf(ss), 1e-12f);
    __nv_bfloat16 ob[8];
#pragma unroll
    for (int e = 0; e < 8; e++) {
        float v = x[e] * rinv;
        g_qn[row * KDIM + lane * 8 + e] = v;
        ob[e] = __float2bfloat16(v);
    }
    *(uint4*)(g_qbf + row * KDIM + lane * 8) = *(uint4*)ob;
}

// ---- kernel 2: normalize keys -> bf16 row-major ----
__global__ void keysprep_kernel(const float* __restrict__ keys) {
    int row  = (blockIdx.x * blockDim.x + threadIdx.x) >> 5;
    int lane = threadIdx.x & 31;
    if (row >= NCORP) return;
    float x[8];
    *(float4*)&x[0] = *(const float4*)(keys + (size_t)row * KDIM + lane * 8);
    *(float4*)&x[4] = *(const float4*)(keys + (size_t)row * KDIM + lane * 8 + 4);
    float ss = 0.f;
#pragma unroll
    for (int e = 0; e < 8; e++) ss += x[e] * x[e];
#pragma unroll
    for (int o = 16; o > 0; o >>= 1) ss += __shfl_xor_sync(0xffffffffu, ss, o);
    float rinv = 1.0f / fmaxf(sqrtf(ss), 1e-12f);
    __nv_bfloat16 ob[8];
#pragma unroll
    for (int e = 0; e < 8; e++) ob[e] = __float2bfloat16(x[e] * rinv);
    *(uint4*)(g_keysN + (size_t)row * KDIM + lane * 8) = *(uint4*)ob;
}

// ---- kernel 3: 512-thread mma.sync GEMM + fused per-chunk top-8 ----
__global__ __launch_bounds__(512, 1) void score_kernel() {
    extern __shared__ char smem[];
    char* sA = smem + SM_A;
    char* sB = smem + SM_B;
    char* sS = smem + SM_S;

    const int t = threadIdx.x, lane = t & 31, wid = t >> 5;
    const int wm = wid >> 2, wn = wid & 3;          // 4x4 warp grid, 32x32 tiles
    const int q0 = blockIdx.x * TM;
    const int c0 = blockIdx.y * CHUNK;

    // A resident fill: 128 rows x 512B
#pragma unroll
    for (int i = 0; i < 8; i++) {
        int u = i * 512 + t; int row = u >> 5, seg = u & 31;
        uint4 v = *(const uint4*)(g_qbf + (size_t)(q0 + row) * KDIM + seg * 8);
        *(uint4*)(sA + row * LDA_B + seg * 16) = v;
    }

    // ldsm base addresses
    unsigned aAddr[2];
    {
        int r = lane & 15, c8 = lane >> 4;
#pragma unroll
        for (int mi = 0; mi < 2; mi++)
            aAddr[mi] = smem_u32(sA + (wm * 32 + mi * 16 + r) * LDA_B + c8 * 16);
    }
    unsigned bAddr[2][2];
    {
        int bn = (lane & 7) + ((lane >> 4) << 3);
        int bk = ((lane >> 3) & 1) * 16;
#pragma unroll
        for (int buf = 0; buf < 2; buf++)
#pragma unroll
            for (int np = 0; np < 2; np++)
                bAddr[buf][np] = smem_u32(sB + buf * SB_BYTES +
                                          (wn * 32 + np * 16 + bn) * LDB_B + bk);
    }

    // per-thread scan state: thread owns query (t>>2), quarter (t&3)
    const int qown = t >> 2, qtr = t & 3;
    float ts[8]; int ti[8];
#pragma unroll
    for (int j = 0; j < 8; j++) { ts[j] = -INFINITY; ti[j] = 0x7fffffff; }

    // cp.async producer for slab gs into buffer buf
    auto issue_B = [&](int gs, int buf) {
        const int nt = gs >> 1, s = gs & 1;
        const __nv_bfloat16* src = g_keysN + (size_t)(c0 + nt * TN) * KDIM + s * KSLAB;
        char* dst = sB + buf * SB_BYTES;
#pragma unroll
        for (int i = 0; i < 4; i++) {
            int u = i * 512 + t; int row = u >> 4, seg = u & 15;
            CP_ASYNC16(smem_u32(dst + row * LDB_B + seg * 16),
                       (const void*)(src + (size_t)row * KDIM + seg * 8));
        }
    };

    float acc[2][4][4];

    issue_B(0, 0); CP_COMMIT();

    for (int gs = 0; gs < NSLABS_TOTAL; gs++) {
        const int buf = gs & 1, s = gs & 1, nt = gs >> 1;
        if (gs + 1 < NSLABS_TOTAL) { issue_B(gs + 1, buf ^ 1); CP_COMMIT(); CP_WAIT1(); }
        else CP_WAIT0();
        __syncthreads();

        if (s == 0) {
#pragma unroll
            for (int mi = 0; mi < 2; mi++)
#pragma unroll
                for (int nf = 0; nf < 4; nf++)
#pragma unroll
                    for (int e = 0; e < 4; e++) acc[mi][nf][e] = 0.f;
        }

        // 8 k16 steps over this 128-K slab
#pragma unroll
        for (int kk = 0; kk < 8; kk++) {
            unsigned af[2][4], bf[2][4];
            const int aofs = s * 256 + kk * 32;
            const int bofs = kk * 32;
#pragma unroll
            for (int mi = 0; mi < 2; mi++) ldsm_x4(af[mi], aAddr[mi] + aofs);
#pragma unroll
            for (int np = 0; np < 2; np++) ldsm_x4(bf[np], bAddr[buf][np] + bofs);
#pragma unroll
            for (int mi = 0; mi < 2; mi++) {
#pragma unroll
                for (int np = 0; np < 2; np++) {
                    mma16816(acc[mi][np * 2 + 0], af[mi], &bf[np][0]);
                    mma16816(acc[mi][np * 2 + 1], af[mi], &bf[np][2]);
                }
            }
        }

        if (s == 1) {
            // stage tile scores to sS as bf16
#pragma unroll
            for (int mi = 0; mi < 2; mi++) {
#pragma unroll
                for (int nf = 0; nf < 4; nf++) {
                    int r0 = wm * 32 + mi * 16 + (lane >> 2);
                    int cc = wn * 32 + nf * 8 + (lane & 3) * 2;
                    *(__nv_bfloat162*)(sS + r0 * LDS_B + cc * 2) =
                        __floats2bfloat162_rn(acc[mi][nf][0], acc[mi][nf][1]);
                    *(__nv_bfloat162*)(sS + (r0 + 8) * LDS_B + cc * 2) =
                        __floats2bfloat162_rn(acc[mi][nf][2], acc[mi][nf][3]);
                }
            }
            __syncthreads();
            // scan 32 cols: group-max filter then detail insert
            {
                const int cbase = c0 + nt * TN + qtr * 32;
                const uint4* p = (const uint4*)(sS + qown * LDS_B + qtr * 64);
#pragma unroll
                for (int g = 0; g < 4; g++) {
                    uint4 v = p[g];
                    __nv_bfloat162 x0 = *(__nv_bfloat162*)&v.x;
                    __nv_bfloat162 x1 = *(__nv_bfloat162*)&v.y;
                    __nv_bfloat162 x2 = *(__nv_bfloat162*)&v.z;
                    __nv_bfloat162 x3 = *(__nv_bfloat162*)&v.w;
                    __nv_bfloat162 m = __hmax2(__hmax2(x0, x1), __hmax2(x2, x3));
                    float gm = fmaxf(__bfloat162float(m.x), __bfloat162float(m.y));
                    if (gm > ts[7]) {
                        int b8 = cbase + g * 8;
                        float e0 = __bfloat162float(x0.x), e1 = __bfloat162float(x0.y);
                        float e2 = __bfloat162float(x1.x), e3 = __bfloat162float(x1.y);
                        float e4 = __bfloat162float(x2.x), e5 = __bfloat162float(x2.y);
                        float e6 = __bfloat162float(x3.x), e7 = __bfloat162float(x3.y);
                        if (e0 > ts[7]) ins8(ts, ti, e0, b8 + 0);
                        if (e1 > ts[7]) ins8(ts, ti, e1, b8 + 1);
                        if (e2 > ts[7]) ins8(ts, ti, e2, b8 + 2);
                        if (e3 > ts[7]) ins8(ts, ti, e3, b8 + 3);
                        if (e4 > ts[7]) ins8(ts, ti, e4, b8 + 4);
                        if (e5 > ts[7]) ins8(ts, ti, e5, b8 + 5);
                        if (e6 > ts[7]) ins8(ts, ti, e6, b8 + 6);
                        if (e7 > ts[7]) ins8(ts, ti, e7, b8 + 7);
                    }
                }
            }
            __syncthreads();
        } else {
            __syncthreads();   // protect buf before next-next prefetch
        }
    }

    // CTA merge: 4 depth-8 lists per query -> chunk top-8
    float* mv = (float*)sS;                 // 512*8 floats = 16KB
    int*   mi2 = (int*)(mv + 512 * 8);      // 16KB
#pragma unroll
    for (int j = 0; j < 8; j++) {
        mv[t * 8 + j] = ts[j]; mi2[t * 8 + j] = ti[j];
    }
    __syncthreads();
    if (t < 128) {
        int p[4] = {0, 0, 0, 0};
        const int Lb = t * 4;
        size_t base = ((size_t)(q0 + t) * NCHUNKS + blockIdx.y) * TOPK;
#pragma unroll
        for (int j = 0; j < TOPK; j++) {
            float bv = -INFINITY; int bi = 0x7fffffff, bl = 0;
#pragma unroll
            for (int l = 0; l < 4; l++) {
                float v = mv[(Lb + l) * 8 + p[l]];
                int   id = mi2[(Lb + l) * 8 + p[l]];
                if (better(v, id, bv, bi)) { bv = v; bi = id; bl = l; }
            }
            p[bl]++;
            g_pscore[base + j] = bv;
            g_pidx[base + j]   = bi;
        }
    }
}

// ---- kernel 4: warp-per-query prune -> approx top-32 ----
__global__ __launch_bounds__(256) void prune_kernel() {
    const int wid = threadIdx.x >> 5, lane = threadIdx.x & 31;
    const int q = blockIdx.x * 8 + wid;
    const float* ps = g_pscore + (size_t)q * NCHUNKS * TOPK;
    const int*   pi = g_pidx   + (size_t)q * NCHUNKS * TOPK;

    float ts[8]; int ti[8];
#pragma unroll
    for (int j = 0; j < 8; j++) { ts[j] = -INFINITY; ti[j] = 0x7fffffff; }
#pragma unroll 4
    for (int pass = 0; pass < 32; pass++) {
        int e = pass * 32 + lane;
        float v = ps[e];
        if (v > ts[7]) ins8(ts, ti, v, pi[e]);
    }
    // 32 rounds of warp argmax (total order via (v, idx)): pop winners
    int p = 0;
    for (int r = 0; r < NCAND; r++) {
        float v = (p < 8) ? ts[p] : -INFINITY;
        int   id = (p < 8) ? ti[p] : 0x7fffffff;
        int   src = lane;
        float bv = v; int bi = id; int bs = src;
#pragma unroll
        for (int o = 16; o > 0; o >>= 1) {
            float ov = __shfl_xor_sync(0xffffffffu, bv, o);
            int   oi = __shfl_xor_sync(0xffffffffu, bi, o);
            int   os = __shfl_xor_sync(0xffffffffu, bs, o);
            if (ov > bv || (ov == bv && oi < bi)) { bv = ov; bi = oi; bs = os; }
        }
        if (lane == bs) p++;
        if (lane == 0) g_cand[q * NCAND + r] = bi;
    }
}

// ---- kernel 5: exact fp32 rescore + final top-8 ----
__global__ __launch_bounds__(256) void rescore_kernel(const float* __restrict__ keys,
                                                      float* __restrict__ out_scores) {
    __shared__ float cs[NCAND];
    __shared__ int   ci[NCAND];
    int q = blockIdx.x;
    int wid = threadIdx.x >> 5, lane = threadIdx.x & 31;

    float qv[8];
    *(float4*)&qv[0] = *(const float4*)(g_qn + q * KDIM + lane * 8);
    *(float4*)&qv[4] = *(const float4*)(g_qn + q * KDIM + lane * 8 + 4);

    for (int c = wid; c < NCAND; c += 8) {
        int idx = g_cand[q * NCAND + c];
        float kv[8];
        *(float4*)&kv[0] = *(const float4*)(keys + (size_t)idx * KDIM + lane * 8);
        *(float4*)&kv[4] = *(const float4*)(keys + (size_t)idx * KDIM + lane * 8 + 4);
        float ss = 0.f, dt = 0.f;
#pragma unroll
        for (int e = 0; e < 8; e++) { ss += kv[e] * kv[e]; dt += kv[e] * qv[e]; }
#pragma unroll
        for (int o = 16; o > 0; o >>= 1) {
            ss += __shfl_xor_sync(0xffffffffu, ss, o);
            dt += __shfl_xor_sync(0xffffffffu, dt, o);
        }
        if (lane == 0) {
            cs[c] = dt / fmaxf(sqrtf(ss), 1e-12f);
            ci[c] = idx;
        }
    }
    __syncthreads();
    if (threadIdx.x == 0) {
        float ts[TOPK]; int ti[TOPK];
#pragma unroll
        for (int j = 0; j < TOPK; j++) { ts[j] = -INFINITY; ti[j] = 0x7fffffff; }
        for (int c = 0; c < NCAND; c++) {
            float v = cs[c]; int id = ci[c];
            if (better(v, id, ts[TOPK - 1], ti[TOPK - 1])) {
                ts[TOPK - 1] = v; ti[TOPK - 1] = id;
#pragma unroll
                for (int j = TOPK - 1; j > 0; j--) {
                    if (better(ts[j], ti[j], ts[j - 1], ti[j - 1])) {
                        float tf = ts[j]; ts[j] = ts[j - 1]; ts[j - 1] = tf;
                        int   tt = ti[j]; ti[j] = ti[j - 1]; ti[j - 1] = tt;
                    }
                }
            }
        }
#pragma unroll
        for (int j = 0; j < TOPK; j++) {
            out_scores[q * TOPK + j] = ts[j];
            g_topidx[q * TOPK + j]   = ti[j];
        }
    }
}

// ---- kernel 6: gather docs ----
__global__ void gather_kernel(const float* __restrict__ vals, float* __restrict__ out_docs) {
    int b = blockIdx.x;
    int idx = g_topidx[b];
    const float4* src = (const float4*)(vals + (size_t)idx * DMODEL);
    float4* dst = (float4*)(out_docs + (size_t)b * DMODEL);
    dst[threadIdx.x] = src[threadIdx.x];
}

extern "C" void kernel_launch(void* const* d_in, const int* in_sizes, int n_in,
                              void* d_out, int out_size) {
    const float* query = (const float*)d_in[0];
    const float* keys  = (const float*)d_in[1];
    const float* vals  = (const float*)d_in[2];
    float* out        = (float*)d_out;
    float* out_docs   = out;
    float* out_scores = out + (size_t)B_Q * TOPK * DMODEL;

    qnorm_kernel<<<B_Q / 8, 256>>>(query);
    keysprep_kernel<<<NCORP / 8, 256>>>(keys);

    cudaFuncSetAttribute(score_kernel,
                         cudaFuncAttributeMaxDynamicSharedMemorySize, SMEM_TOTAL);
    score_kernel<<<dim3(QTILES, NCHUNKS), 512, SMEM_TOTAL>>>();

    prune_kernel<<<B_Q / 8, 256>>>();
    rescore_kernel<<<B_Q, 256>>>(keys, out_scores);
    gather_kernel<<<B_Q * TOPK, 256>>>(vals, out_docs);
}